// round 2
// baseline (speedup 1.0000x reference)
#include <cuda_runtime.h>
#include <math.h>

#define B   4096
#define L   200
#define LF  100
#define E   64
#define P   32
#define H   32
#define IFD 128
#define TPD 3168   /* P + PNET = 32 + 3136 */

// ---------------- scratch (device globals: allowed, no runtime alloc) ----------------
__device__ float g_prompt_input[B * E];                  // 1 MB
__device__ float g_total_prompt[(size_t)B * TPD];        // ~52 MB
__device__ float g_final_user[B * E];
__device__ float g_final_item[B * E];
__device__ float g_pos_pe[B * P];

// ======================================================================
// K1: per-batch gather + attention pooling + feature MLPs + prompt_input
// ======================================================================
__global__ __launch_bounds__(256) void k1_kernel(
    const float* __restrict__ item_emb, const float* __restrict__ user_emb,
    const float* __restrict__ W_if, const float* __restrict__ b_if,
    const float* __restrict__ W_uf, const float* __restrict__ b_uf,
    const float* __restrict__ item_features, const float* __restrict__ user_features,
    const int* __restrict__ user_id, const int* __restrict__ target_item_id,
    const int* __restrict__ history_item_id, const int* __restrict__ history_len,
    const int* __restrict__ item_pos_feedback, const int* __restrict__ pos_mask)
{
    int b = blockIdx.x;
    int tid = threadIdx.x;

    __shared__ float s_tgt[E];
    __shared__ float s_feat[IFD];
    __shared__ float s_ife[E];
    __shared__ float s_ufe[E];
    __shared__ float s_attn[L];
    __shared__ int   s_hidx[L];
    __shared__ int   s_pidx[LF];
    __shared__ float s_pm[LF];
    __shared__ float red[256];

    int tgt_id = target_item_id[b];
    if (tid < E)   s_tgt[tid]  = item_emb[(size_t)tgt_id * E + tid];
    if (tid < IFD) s_feat[tid] = item_features[(size_t)b * IFD + tid];
    for (int l = tid; l < L; l += 256)  s_hidx[l] = history_item_id[(size_t)b * L + l];
    for (int l = tid; l < LF; l += 256) {
        s_pidx[l] = item_pos_feedback[(size_t)b * LF + l];
        s_pm[l]   = pos_mask[(size_t)b * LF + l] ? 1.0f : 0.0f;
    }
    __syncthreads();

    // item feature MLP: sigmoid(feat @ W_if + b_if)
    if (tid < E) {
        float a = b_if[tid];
        #pragma unroll 8
        for (int k = 0; k < IFD; k++) a += s_feat[k] * W_if[k * E + tid];
        s_ife[tid] = 1.0f / (1.0f + expf(-a));
    }
    __syncthreads();
    if (tid < IFD) s_feat[tid] = user_features[(size_t)b * IFD + tid];
    __syncthreads();
    if (tid < E) {
        float a = b_uf[tid];
        #pragma unroll 8
        for (int k = 0; k < IFD; k++) a += s_feat[k] * W_uf[k * E + tid];
        s_ufe[tid] = 1.0f / (1.0f + expf(-a));
    }
    __syncthreads();

    // attention scores
    int hlen = history_len[b];
    float sc = -1e30f;
    if (tid < L) {
        const float4* row = (const float4*)(item_emb + (size_t)s_hidx[tid] * E);
        float d = 0.0f;
        #pragma unroll
        for (int q = 0; q < 16; q++) {
            float4 v = row[q];
            d += v.x * s_tgt[4*q] + v.y * s_tgt[4*q+1] + v.z * s_tgt[4*q+2] + v.w * s_tgt[4*q+3];
        }
        sc = (tid < hlen) ? d * 0.125f : -1e9f;
    }
    // softmax: max
    red[tid] = sc; __syncthreads();
    for (int s = 128; s > 0; s >>= 1) { if (tid < s) red[tid] = fmaxf(red[tid], red[tid+s]); __syncthreads(); }
    float mx = red[0]; __syncthreads();
    float ex = (tid < L) ? expf(sc - mx) : 0.0f;
    red[tid] = ex; __syncthreads();
    for (int s = 128; s > 0; s >>= 1) { if (tid < s) red[tid] += red[tid+s]; __syncthreads(); }
    float inv = 1.0f / red[0];
    if (tid < L) s_attn[tid] = ex * inv;
    __syncthreads();

    // pooled history + outputs (threads 0..63 = embedding dim)
    if (tid < E) {
        float acc = 0.0f;
        for (int l = 0; l < L; l++)
            acc += s_attn[l] * item_emb[(size_t)s_hidx[l] * E + tid];
        int uid = user_id[b];
        g_final_user[b * E + tid] = user_emb[(size_t)uid * E + tid] + s_ufe[tid] + acc;
        g_final_item[b * E + tid] = s_tgt[tid] + s_ife[tid];

        float cnt = 0.0f, pacc = 0.0f;
        for (int l = 0; l < LF; l++) {
            float m = s_pm[l];
            cnt  += m;
            pacc += m * item_emb[(size_t)s_pidx[l] * E + tid];
        }
        g_prompt_input[b * E + tid] = pacc / cnt;
    }
}

// ======================================================================
// K2: total_prompt = relu(prompt_input[B,64] @ Wp[64,3168] + bp)
// Tiled: 64 batch rows per block, 792 cols per blockIdx.y (4 * 792 = 3168)
// ======================================================================
__global__ __launch_bounds__(256) void k2_kernel(
    const float* __restrict__ Wp, const float* __restrict__ bp)
{
    int b0 = blockIdx.x * 64;
    int jb = blockIdx.y * 792;
    __shared__ float sA[64 * 64];
    for (int t = threadIdx.x; t < 64 * 64; t += 256)
        sA[t] = g_prompt_input[(b0 + (t >> 6)) * E + (t & 63)];
    __syncthreads();

    for (int t = threadIdx.x; t < 4 * 792; t += 256) {
        int rg = t / 792;
        int j  = jb + (t - rg * 792);
        float acc[16];
        #pragma unroll
        for (int r = 0; r < 16; r++) acc[r] = 0.0f;
        const float* wcol = Wp + j;
        #pragma unroll 4
        for (int k = 0; k < 64; k++) {
            float w = wcol[(size_t)k * TPD];
            #pragma unroll
            for (int r = 0; r < 16; r++) acc[r] += sA[(rg * 16 + r) * 64 + k] * w;
        }
        float bb = bp[j];
        #pragma unroll
        for (int r = 0; r < 16; r++) {
            float v = acc[r] + bb;
            g_total_prompt[(size_t)(b0 + rg * 16 + r) * TPD + j] = v > 0.0f ? v : 0.0f;
        }
    }
}

// ======================================================================
// K3: per-sample prompt MLP on pos & neg feedback, masked sums, loss
// block = one batch element; 256 threads = 8 items x 32 units
// ======================================================================
__global__ __launch_bounds__(256) void k3_kernel(
    const float* __restrict__ item_emb,
    const int* __restrict__ pos_fb, const int* __restrict__ pos_mask,
    const int* __restrict__ neg_fb, const int* __restrict__ neg_mask,
    float* __restrict__ out)
{
    int b = blockIdx.x;
    int tid = threadIdx.x;
    const float* tp = g_total_prompt + (size_t)b * TPD;

    __shared__ float w1s[2048];  // [E=64][H=32]
    __shared__ float b1s[32];
    __shared__ float w2s[1024];  // [H=32][P=32]
    __shared__ float b2s[32];
    __shared__ float us[8 * 64];
    __shared__ float hs[8 * 32];
    __shared__ float ms[8];
    __shared__ float red[256];
    __shared__ float pe[2][32];

    for (int t = tid; t < 2048; t += 256) w1s[t] = tp[32 + t];
    for (int t = tid; t < 1024; t += 256) w2s[t] = tp[2112 + t];
    if (tid < 32) { b1s[tid] = tp[2080 + tid]; b2s[tid] = tp[3136 + tid]; }
    __syncthreads();

    int i = tid >> 5;     // item within group (0..7)
    int p = tid & 31;     // unit index

    for (int br = 0; br < 2; br++) {
        const int* fb = br ? neg_fb : pos_fb;
        const int* mk = br ? neg_mask : pos_mask;
        float acc = 0.0f;
        for (int g = 0; g < 13; g++) {         // 13 groups of 8 covers LF=100
            for (int t = tid; t < 512; t += 256) {
                int it = t >> 6, e = t & 63;
                int ig = g * 8 + it;
                us[t] = (ig < LF) ? item_emb[(size_t)fb[(size_t)b * LF + ig] * E + e] : 0.0f;
            }
            if (tid < 8) {
                int ig = g * 8 + tid;
                ms[tid] = (ig < LF && mk[(size_t)b * LF + ig]) ? 1.0f : 0.0f;
            }
            __syncthreads();

            float hv = b1s[p];
            #pragma unroll
            for (int e = 0; e < 64; e++) hv += us[i * 64 + e] * w1s[e * 32 + p];
            hs[i * 32 + p] = hv > 0.0f ? hv : 0.0f;
            __syncthreads();

            float ov = b2s[p];
            #pragma unroll
            for (int h = 0; h < 32; h++) ov += hs[i * 32 + h] * w2s[h * 32 + p];
            acc += ms[i] * ov;
            __syncthreads();
        }
        red[tid] = acc; __syncthreads();
        if (tid < 32) {
            float s = 0.0f;
            #pragma unroll
            for (int q = 0; q < 8; q++) s += red[q * 32 + tid];
            pe[br][tid] = s;
        }
        __syncthreads();
    }

    if (tid < 32) {
        float pos = pe[0][tid], neg = pe[1][tid];
        g_pos_pe[b * 32 + tid] = pos;
        float x = neg - pos;  // softplus(-(pos-neg)) == softplus(neg-pos)
        out[B + b * 32 + tid] = fmaxf(x, 0.0f) + log1pf(expf(-fabsf(x)));
    }
}

// ======================================================================
// K4: fusion MLP (128->200->80->64) + final dot product. 8 rows / block.
// ======================================================================
__global__ __launch_bounds__(256) void k4_kernel(
    const float* __restrict__ Wf1, const float* __restrict__ bf1,
    const float* __restrict__ Wf2, const float* __restrict__ bf2,
    const float* __restrict__ Wf3, float* __restrict__ out)
{
    int b0 = blockIdx.x * 8;
    int tid = threadIdx.x;
    __shared__ float fin[8 * 128];
    __shared__ float h1[8 * 200];
    __shared__ float h2[8 * 80];
    __shared__ float fu[8 * 64];

    for (int t = tid; t < 8 * 128; t += 256) {
        int r = t >> 7, c = t & 127;
        int b = b0 + r;
        float v;
        if (c < 64)      v = g_final_item[b * 64 + c];
        else if (c < 96) v = g_pos_pe[b * 32 + (c - 64)];
        else             v = g_total_prompt[(size_t)b * TPD + (c - 96)];
        fin[t] = v;
    }
    __syncthreads();

    if (tid < 200) {
        float acc[8];
        #pragma unroll
        for (int r = 0; r < 8; r++) acc[r] = bf1[tid];
        for (int k = 0; k < 128; k++) {
            float w = Wf1[k * 200 + tid];
            #pragma unroll
            for (int r = 0; r < 8; r++) acc[r] += fin[r * 128 + k] * w;
        }
        #pragma unroll
        for (int r = 0; r < 8; r++) h1[r * 200 + tid] = acc[r] > 0.0f ? acc[r] : 0.0f;
    }
    __syncthreads();

    if (tid < 80) {
        float acc[8];
        #pragma unroll
        for (int r = 0; r < 8; r++) acc[r] = bf2[tid];
        for (int k = 0; k < 200; k++) {
            float w = Wf2[k * 80 + tid];
            #pragma unroll
            for (int r = 0; r < 8; r++) acc[r] += h1[r * 200 + k] * w;
        }
        #pragma unroll
        for (int r = 0; r < 8; r++) h2[r * 80 + tid] = acc[r] > 0.0f ? acc[r] : 0.0f;
    }
    __syncthreads();

    if (tid < 64) {
        float acc[8];
        #pragma unroll
        for (int r = 0; r < 8; r++) acc[r] = 0.0f;
        for (int k = 0; k < 80; k++) {
            float w = Wf3[k * 64 + tid];
            #pragma unroll
            for (int r = 0; r < 8; r++) acc[r] += h2[r * 80 + k] * w;
        }
        #pragma unroll
        for (int r = 0; r < 8; r++) fu[r * 64 + tid] = acc[r];
    }
    __syncthreads();

    int r = tid >> 5, lane = tid & 31;
    int b = b0 + r;
    float par = g_final_user[b * 64 + lane]      * fu[r * 64 + lane]
              + g_final_user[b * 64 + 32 + lane] * fu[r * 64 + 32 + lane];
    #pragma unroll
    for (int s = 16; s > 0; s >>= 1) par += __shfl_xor_sync(0xffffffff, par, s);
    if (lane == 0) out[b] = par;
}

// ======================================================================
extern "C" void kernel_launch(void* const* d_in, const int* in_sizes, int n_in,
                              void* d_out, int out_size)
{
    const float* item_emb        = (const float*)d_in[0];
    const float* user_emb        = (const float*)d_in[1];
    const float* W_if            = (const float*)d_in[2];
    const float* b_if            = (const float*)d_in[3];
    const float* W_uf            = (const float*)d_in[4];
    const float* b_uf            = (const float*)d_in[5];
    const float* Wp              = (const float*)d_in[6];
    const float* bp              = (const float*)d_in[7];
    const float* Wf1             = (const float*)d_in[8];
    const float* bf1             = (const float*)d_in[9];
    const float* Wf2             = (const float*)d_in[10];
    const float* bf2             = (const float*)d_in[11];
    const float* Wf3             = (const float*)d_in[12];
    const float* item_features   = (const float*)d_in[13];
    const float* user_features   = (const float*)d_in[14];
    const int*   user_id         = (const int*)d_in[15];
    const int*   target_item_id  = (const int*)d_in[16];
    const int*   history_item_id = (const int*)d_in[17];
    const int*   history_len     = (const int*)d_in[18];
    const int*   pos_fb          = (const int*)d_in[19];
    const int*   pos_mask        = (const int*)d_in[20];
    const int*   neg_fb          = (const int*)d_in[21];
    const int*   neg_mask        = (const int*)d_in[22];
    float* out = (float*)d_out;

    k1_kernel<<<B, 256>>>(item_emb, user_emb, W_if, b_if, W_uf, b_uf,
                          item_features, user_features, user_id, target_item_id,
                          history_item_id, history_len, pos_fb, pos_mask);
    k2_kernel<<<dim3(64, 4), 256>>>(Wp, bp);
    k3_kernel<<<B, 256>>>(item_emb, pos_fb, pos_mask, neg_fb, neg_mask, out);
    k4_kernel<<<B / 8, 256>>>(Wf1, bf1, Wf2, bf2, Wf3, out);
}